// round 1
// baseline (speedup 1.0000x reference)
#include <cuda_runtime.h>

// Problem constants (match reference)
#define POOL      7
#define NUM_ROIS  300
#define FH        200
#define FW        200
#define FC        512

// One block per (cell, roi); cell = py*7+px. 128 threads, 4 channels each (float4).
__global__ __launch_bounds__(128, 8)
void roi_pool_kernel(const float* __restrict__ feat,
                     const int*   __restrict__ rois,
                     float*       __restrict__ out)
{
    const int cell = blockIdx.x;          // 0..48
    const int roi  = blockIdx.y;          // 0..299
    const int py   = cell / POOL;
    const int px   = cell % POOL;

    // ROI params (same for all threads — tiny ALU cost)
    const int x0 = rois[roi * 4 + 0];
    const int y0 = rois[roi * 4 + 1];
    const int w  = rois[roi * 4 + 2];
    const int h  = rois[roi * 4 + 3];

    // Exact reference arithmetic: sy = py * (h/7), fp32 throughout
    const float hs = (float)h / (float)POOL;
    const float ws = (float)w / (float)POOL;
    const float sy = (float)py * hs;
    const float sx = (float)px * ws;

    const int y_lo = (int)floorf(sy);
    const int x_lo = (int)floorf(sx);
    const int y_hi = min(y_lo + 1, h - 1);
    const int x_hi = min(x_lo + 1, w - 1);

    const float fy = sy - (float)y_lo;
    const float fx = sx - (float)x_lo;

    const int ay_lo = y0 + y_lo;
    const int ay_hi = y0 + y_hi;
    const int ax_lo = x0 + x_lo;
    const int ax_hi = x0 + x_hi;

    const float w00 = (1.0f - fy) * (1.0f - fx);
    const float w01 = (1.0f - fy) * fx;
    const float w10 = fy * (1.0f - fx);
    const float w11 = fy * fx;

    // Corner pixel base pointers (channel-contiguous, 2KB each)
    const float4* __restrict__ p00 = (const float4*)(feat + ((size_t)ay_lo * FW + ax_lo) * FC);
    const float4* __restrict__ p01 = (const float4*)(feat + ((size_t)ay_lo * FW + ax_hi) * FC);
    const float4* __restrict__ p10 = (const float4*)(feat + ((size_t)ay_hi * FW + ax_lo) * FC);
    const float4* __restrict__ p11 = (const float4*)(feat + ((size_t)ay_hi * FW + ax_hi) * FC);

    float4* __restrict__ po = (float4*)(out + ((size_t)roi * (POOL * POOL) + cell) * FC);

    const int t = threadIdx.x;            // 0..127, each owns 4 channels
    // FC/4 = 128 float4 elements exactly -> one float4 per thread
    const float4 v00 = p00[t];
    const float4 v01 = p01[t];
    const float4 v10 = p10[t];
    const float4 v11 = p11[t];

    float4 r;
    r.x = w00 * v00.x + w01 * v01.x + w10 * v10.x + w11 * v11.x;
    r.y = w00 * v00.y + w01 * v01.y + w10 * v10.y + w11 * v11.y;
    r.z = w00 * v00.z + w01 * v01.z + w10 * v10.z + w11 * v11.z;
    r.w = w00 * v00.w + w01 * v01.w + w10 * v10.w + w11 * v11.w;

    po[t] = r;
}

extern "C" void kernel_launch(void* const* d_in, const int* in_sizes, int n_in,
                              void* d_out, int out_size)
{
    const float* feat = (const float*)d_in[0];   // (1,200,200,512) f32
    const int*   rois = (const int*)d_in[1];     // (1,300,4) i32
    float*       out  = (float*)d_out;           // (1,300,7,7,512) f32

    dim3 grid(POOL * POOL, NUM_ROIS);
    roi_pool_kernel<<<grid, 128>>>(feat, rois, out);
}